// round 5
// baseline (speedup 1.0000x reference)
#include <cuda_runtime.h>
#include <math.h>
#include <stdint.h>

#define U_N 4000
#define P_N 4000
#define G_N 200
#define D   64
#define B_N 512
#define NUP (U_N + P_N)   // 8000
#define NGU (G_N + U_N)   // 4200
#define NGP (G_N + P_N)   // 4200
#define NTOT (NUP + NGU + NGP)

// ---------------- scratch (device globals; no allocation allowed) ----------
__device__ __align__(16) float g_Xup[NUP * D];
__device__ __align__(16) float g_Xgu[NGU * D];
__device__ __align__(16) float g_Xgp[NGP * D];
__device__ __align__(16) float g_Rup[NUP * D];
__device__ __align__(16) float g_Rgu[NGU * D];
__device__ __align__(16) float g_Rgp[NGP * D];
__device__ float g_deg[NTOT];
__device__ __align__(16) float g_uf[B_N * D];
__device__ __align__(16) float g_q [B_N * D];

// ---------------- init: zero accumulators + build concatenated X -----------
__global__ void init_all(const float* __restrict__ ue,
                         const float* __restrict__ pe,
                         const float* __restrict__ ge)
{
    int i = blockIdx.x * blockDim.x + threadIdx.x;
    if (i < NUP * D) {
        g_Rup[i] = 0.f;
        g_Xup[i] = (i < U_N * D) ? ue[i] : pe[i - U_N * D];
    }
    if (i < NGU * D) {
        g_Rgu[i] = 0.f;
        g_Rgp[i] = 0.f;
        g_Xgu[i] = (i < G_N * D) ? ge[i] : ue[i - G_N * D];
        g_Xgp[i] = (i < G_N * D) ? ge[i] : pe[i - G_N * D];
    }
    if (i < NTOT) g_deg[i] = 0.f;
}

// ---------------- helpers ----------------------------------------------------
__device__ __forceinline__ unsigned smem_u32(const void* p)
{
    return (unsigned)__cvta_generic_to_shared(p);
}

__device__ __forceinline__ void mbar_init(unsigned mb, int count)
{
    asm volatile("mbarrier.init.shared.b64 [%0], %1;" :: "r"(mb), "r"(count) : "memory");
}
__device__ __forceinline__ void mbar_expect_tx(unsigned mb, unsigned bytes)
{
    asm volatile("mbarrier.arrive.expect_tx.shared.b64 _, [%0], %1;"
                 :: "r"(mb), "r"(bytes) : "memory");
}
__device__ __forceinline__ void mbar_wait(unsigned mb, int phase)
{
    asm volatile(
        "{\n\t"
        ".reg .pred P;\n\t"
        "W_%=:\n\t"
        "mbarrier.try_wait.parity.acquire.cta.shared::cta.b64 P, [%0], %1, 0x989680;\n\t"
        "@P bra D_%=;\n\t"
        "bra W_%=;\n\t"
        "D_%=:\n\t"
        "}"
        :: "r"(mb), "r"(phase) : "memory");
}
__device__ __forceinline__ void bulk_cp(unsigned smem_dst, const void* gmem_src,
                                        unsigned bytes, unsigned mb)
{
    asm volatile(
        "cp.async.bulk.shared::cluster.global.mbarrier::complete_tx::bytes [%0], [%1], %2, [%3];"
        :: "r"(smem_dst), "l"(gmem_src), "r"(bytes), "r"(mb) : "memory");
}

__device__ __forceinline__ void mma_tf32(
    float& c0, float& c1, float& c2, float& c3,
    unsigned a0, unsigned a1, unsigned a2, unsigned a3,
    unsigned b0, unsigned b1)
{
    asm volatile(
        "mma.sync.aligned.m16n8k8.row.col.f32.tf32.tf32.f32 "
        "{%0,%1,%2,%3}, {%4,%5,%6,%7}, {%8,%9}, {%0,%1,%2,%3};\n"
        : "+f"(c0), "+f"(c1), "+f"(c2), "+f"(c3)
        : "r"(a0), "r"(a1), "r"(a2), "r"(a3), "r"(b0), "r"(b1));
}

// ---------------- propagation GEMM ------------------------------------------
// R += A@X (tf32 MMA), deg += rowsum(A).
// A: direct gmem->fragment LDG.32 (no smem). X: cp.async.bulk double buffer.
// Tile BM=128 x 64, BK=64. 8 warps x 16 rows, each warp full N=64.
#define BM 128
#define BKK 64
#define XSTR 72
#define XBUF (BKK * XSTR)      // 4608 floats / stage

#define RT0 63
#define RT12 33
#define KS0 8
#define KS12 4
#define NB0 (RT0 * KS0)        // 504
#define NB12 (RT12 * KS12)     // 132
#define NBLK (NB0 + 2 * NB12)  // 768

extern "C" __global__ void __launch_bounds__(256, 2)
gemm_all(const float* __restrict__ A0, const float* __restrict__ A1,
         const float* __restrict__ A2,
         const float* __restrict__ X0, const float* __restrict__ X1,
         const float* __restrict__ X2,
         float* __restrict__ R0, float* __restrict__ R1, float* __restrict__ R2,
         float* __restrict__ degAll)
{
    __shared__ __align__(16) float Xs[2][XBUF];
    __shared__ uint64_t mbar[2];

    const int tid  = threadIdx.x;
    const int lane = tid & 31;
    const int warp = tid >> 5;
    const int rq   = lane >> 2;
    const int kc   = lane & 3;

    // ---- map block -> (problem, rowTile, ksplit) ----
    const float *A, *X; float *R, *deg;
    int n, rowTiles, kIters, kps, local;
    int b = blockIdx.x;
    if (b < NB0)             { A = A0; X = X0; R = R0; deg = degAll;             n = NUP; rowTiles = RT0;  kIters = 125; kps = 16; local = b; }
    else if (b < NB0 + NB12) { A = A1; X = X1; R = R1; deg = degAll + NUP;       n = NGU; rowTiles = RT12; kIters = 66;  kps = 17; local = b - NB0; }
    else                     { A = A2; X = X2; R = R2; deg = degAll + NUP + NGU; n = NGP; rowTiles = RT12; kIters = 66;  kps = 17; local = b - NB0 - NB12; }

    const int rowTile = local % rowTiles;
    const int split   = local / rowTiles;
    const int rowBase = rowTile * BM;
    const int itStart = split * kps;
    const int itEnd   = min(kIters, itStart + kps);
    const int nIt     = itEnd - itStart;
    if (nIt <= 0) return;
    const int kEnd = min(n, itEnd * BKK);

    // zero stale smem (NaN-safety for tail rows / first iters)
    for (int i = tid; i < 2 * XBUF; i += 256) ((float*)Xs)[i] = 0.f;
    if (tid == 0) { mbar_init(smem_u32(&mbar[0]), 1); mbar_init(smem_u32(&mbar[1]), 1); }
    __syncthreads();

    // prologue: issue X tile for iter 0
    if (tid == 0) {
        int k0 = itStart * BKK;
        int rows = min(BKK, kEnd - k0);
        unsigned mb = smem_u32(&mbar[0]);
        mbar_expect_tx(mb, rows * 256);
        unsigned dst = smem_u32(&Xs[0][0]);
        #pragma unroll 4
        for (int r = 0; r < rows; r++)
            bulk_cp(dst + r * (XSTR * 4), X + (size_t)(k0 + r) * D, 256, mb);
    }

    float c[8][4];
    #pragma unroll
    for (int nt = 0; nt < 8; nt++)
        #pragma unroll
        for (int j = 0; j < 4; j++) c[nt][j] = 0.f;
    float dacc0 = 0.f, dacc1 = 0.f;

    const int r0 = rowBase + warp * 16 + rq;
    const bool rOk0 = r0 < n;
    const bool rOk1 = (r0 + 8) < n;
    int pha[2] = {0, 0};

    for (int i = 0; i < nIt; i++) {
        const int cur = i & 1;

        // issue next X tile (buffer freed by last iter's __syncthreads)
        if (tid == 0 && i + 1 < nIt) {
            int k0n = (itStart + i + 1) * BKK;
            int rows = min(BKK, kEnd - k0n);
            unsigned mb = smem_u32(&mbar[cur ^ 1]);
            mbar_expect_tx(mb, rows * 256);
            unsigned dst = smem_u32(&Xs[cur ^ 1][0]);
            #pragma unroll 4
            for (int r = 0; r < rows; r++)
                bulk_cp(dst + r * (XSTR * 4), X + (size_t)(k0n + r) * D, 256, mb);
        }

        // A fragments for this iter: direct from gmem (overlaps mbar wait)
        const int k0 = (itStart + i) * BKK;
        float a[8][4];
        #pragma unroll
        for (int ks = 0; ks < 8; ks++) {
            int k = k0 + ks * 8 + kc;
            bool kOk0 = k < kEnd;
            bool kOk1 = (k + 4) < kEnd;
            a[ks][0] = (rOk0 && kOk0) ? __ldg(&A[(size_t)r0 * n + k])           : 0.f;
            a[ks][1] = (rOk1 && kOk0) ? __ldg(&A[(size_t)(r0 + 8) * n + k])     : 0.f;
            a[ks][2] = (rOk0 && kOk1) ? __ldg(&A[(size_t)r0 * n + k + 4])       : 0.f;
            a[ks][3] = (rOk1 && kOk1) ? __ldg(&A[(size_t)(r0 + 8) * n + k + 4]) : 0.f;
        }
        #pragma unroll
        for (int ks = 0; ks < 8; ks++) {
            dacc0 += a[ks][0] + a[ks][2];
            dacc1 += a[ks][1] + a[ks][3];
        }

        mbar_wait(smem_u32(&mbar[cur]), pha[cur]);
        pha[cur] ^= 1;

        const float* Xc = Xs[cur];
        #pragma unroll
        for (int ks = 0; ks < 8; ks++) {
            int kb = ks * 8;
            #pragma unroll
            for (int nt = 0; nt < 8; nt++) {
                int col = nt * 8 + rq;
                unsigned b0 = __float_as_uint(Xc[(kb + kc) * XSTR + col]);
                unsigned b1 = __float_as_uint(Xc[(kb + kc + 4) * XSTR + col]);
                mma_tf32(c[nt][0], c[nt][1], c[nt][2], c[nt][3],
                         __float_as_uint(a[ks][0]), __float_as_uint(a[ks][1]),
                         __float_as_uint(a[ks][2]), __float_as_uint(a[ks][3]),
                         b0, b1);
            }
        }
        __syncthreads();   // release buffers for re-fill
    }

    // ---- deg: reduce over the 4 kc lanes, one atomic per row ----
    {
        float v0 = dacc0, v1 = dacc1;
        v0 += __shfl_xor_sync(0xffffffffu, v0, 1);
        v0 += __shfl_xor_sync(0xffffffffu, v0, 2);
        v1 += __shfl_xor_sync(0xffffffffu, v1, 1);
        v1 += __shfl_xor_sync(0xffffffffu, v1, 2);
        if (kc == 0) {
            if (rOk0) atomicAdd(&deg[r0], v0);
            if (rOk1) atomicAdd(&deg[r0 + 8], v1);
        }
    }

    // ---- accumulate split-K partials ----
    const int ccBase = kc * 2;
    #pragma unroll
    for (int nt = 0; nt < 8; nt++) {
        int cc = nt * 8 + ccBase;
        if (rOk0) {
            atomicAdd(&R[r0 * D + cc],     c[nt][0]);
            atomicAdd(&R[r0 * D + cc + 1], c[nt][1]);
        }
        if (rOk1) {
            atomicAdd(&R[(r0 + 8) * D + cc],     c[nt][2]);
            atomicAdd(&R[(r0 + 8) * D + cc + 1], c[nt][3]);
        }
    }
}

// ---------------- epilogue: R = (X + R/max(deg,1e-8)) * 0.5 -----------------
__global__ void epilogue_all()
{
    int idx = blockIdx.x * blockDim.x + threadIdx.x;
    if (idx >= NTOT * D) return;
    int row = idx >> 6;
    float d = fmaxf(g_deg[row], 1e-8f);
    if (row < NUP) {
        g_Rup[idx] = (g_Xup[idx] + g_Rup[idx] / d) * 0.5f;
    } else if (row < NUP + NGU) {
        int j = idx - NUP * D;
        g_Rgu[j] = (g_Xgu[j] + g_Rgu[j] / d) * 0.5f;
    } else {
        int j = idx - (NUP + NGU) * D;
        g_Rgp[j] = (g_Xgp[j] + g_Rgp[j] / d) * 0.5f;
    }
}

// ---------------- user_feat gather + q = uf @ W (once, fp32) ----------------
__global__ void uf_q_kernel(const int* __restrict__ uids,
                            const float* __restrict__ W,
                            float* __restrict__ out_uf)
{
    __shared__ float sh[D];
    int b = blockIdx.x;
    int d = threadIdx.x;
    int uid = uids[b];
    float v = 0.5f * (g_Rup[uid * D + d] + g_Rgu[(G_N + uid) * D + d]);
    sh[d] = v;
    g_uf[b * D + d] = v;
    out_uf[b * D + d] = v;
    __syncthreads();
    float acc = 0.f;
    #pragma unroll
    for (int k = 0; k < D; k++) acc += sh[k] * W[k * D + d];
    g_q[b * D + d] = acc;
}

// ---------------- score kernel: tf32 MMA, dots with 3xTF32 compensation -----
// Block: 64 users x 64 papers, 256 thr = 4 warpB(16u) x 2 warpP(32p).
#define SST 72
#define S_SMEM_BYTES (4 * 64 * SST * 4)   // 73728

__device__ __forceinline__ void split13(float x, unsigned& hi, unsigned& lo)
{
    unsigned h = __float_as_uint(x) & 0xFFFFE000u;
    hi = h;
    lo = __float_as_uint(x - __uint_as_float(h));
}

extern "C" __global__ void __launch_bounds__(256, 2)
score_all(float* __restrict__ scores)
{
    extern __shared__ float smem[];
    float* Qs  = smem;                // [64][SST]
    float* Us  = Qs  + 64 * SST;
    float* I0s = Us  + 64 * SST;
    float* I1s = I0s + 64 * SST;

    const int tid   = threadIdx.x;
    const int lane  = tid & 31;
    const int warp  = tid >> 5;
    const int warpB = warp >> 1;
    const int warpP = warp & 1;
    const int rq    = lane >> 2;
    const int kc    = lane & 3;
    const int ub    = blockIdx.y * 64;
    const int pb    = blockIdx.x * 64;

    // load Q/UF (users) and I0/I1 (papers) tiles, k-contiguous float4
    #pragma unroll
    for (int it = 0; it < 4; it++) {
        int slot = tid + it * 256;     // 1024 float4 slots per array
        int r  = slot >> 4;
        int c4 = (slot & 15) << 2;
        float4 q = *reinterpret_cast<const float4*>(&g_q [(size_t)(ub + r) * D + c4]);
        float4 u = *reinterpret_cast<const float4*>(&g_uf[(size_t)(ub + r) * D + c4]);
        *reinterpret_cast<float4*>(&Qs[r * SST + c4]) = q;
        *reinterpret_cast<float4*>(&Us[r * SST + c4]) = u;
        int gp = pb + r;
        float4 v0 = make_float4(0.f, 0.f, 0.f, 0.f), v1 = v0;
        if (gp < P_N) {
            v0 = *reinterpret_cast<const float4*>(&g_Rup[(size_t)(U_N + gp) * D + c4]);
            v1 = *reinterpret_cast<const float4*>(&g_Rgp[(size_t)(G_N + gp) * D + c4]);
        }
        *reinterpret_cast<float4*>(&I0s[r * SST + c4]) = v0;
        *reinterpret_cast<float4*>(&I1s[r * SST + c4]) = v1;
    }
    __syncthreads();

    float l0[4][4] = {}, l1[4][4] = {}, d0[4][4] = {}, d1[4][4] = {};
    const int ar = warpB * 16 + rq;

    #pragma unroll
    for (int ks = 0; ks < 8; ks++) {
        int kb = ks * 8;
        // a-frags: q (raw -> plain tf32) and uf (hi/lo split)
        unsigned aq[4];
        float uf[4];
        aq[0] = __float_as_uint(Qs[ar * SST + kb + kc]);
        aq[1] = __float_as_uint(Qs[(ar + 8) * SST + kb + kc]);
        aq[2] = __float_as_uint(Qs[ar * SST + kb + kc + 4]);
        aq[3] = __float_as_uint(Qs[(ar + 8) * SST + kb + kc + 4]);
        uf[0] = Us[ar * SST + kb + kc];
        uf[1] = Us[(ar + 8) * SST + kb + kc];
        uf[2] = Us[ar * SST + kb + kc + 4];
        uf[3] = Us[(ar + 8) * SST + kb + kc + 4];
        unsigned uh[4], ul[4];
        #pragma unroll
        for (int j = 0; j < 4; j++) split13(uf[j], uh[j], ul[j]);

        #pragma unroll
        for (int nt = 0; nt < 4; nt++) {
            int col = warpP * 32 + nt * 8 + rq;
            float b00f = I0s[col * SST + kb + kc];
            float b01f = I0s[col * SST + kb + kc + 4];
            float b10f = I1s[col * SST + kb + kc];
            float b11f = I1s[col * SST + kb + kc + 4];
            unsigned h00, l00, h01, l01, h10, l10, h11, l11;
            split13(b00f, h00, l00); split13(b01f, h01, l01);
            split13(b10f, h10, l10); split13(b11f, h11, l11);

            // logits: plain tf32
            mma_tf32(l0[nt][0], l0[nt][1], l0[nt][2], l0[nt][3],
                     aq[0], aq[1], aq[2], aq[3], h00, h01);
            mma_tf32(l1[nt][0], l1[nt][1], l1[nt][2], l1[nt][3],
                     aq[0], aq[1], aq[2], aq[3], h10, h11);
            // dots: 3xTF32 compensated
            mma_tf32(d0[nt][0], d0[nt][1], d0[nt][2], d0[nt][3],
                     uh[0], uh[1], uh[2], uh[3], h00, h01);
            mma_tf32(d0[nt][0], d0[nt][1], d0[nt][2], d0[nt][3],
                     uh[0], uh[1], uh[2], uh[3], l00, l01);
            mma_tf32(d0[nt][0], d0[nt][1], d0[nt][2], d0[nt][3],
                     ul[0], ul[1], ul[2], ul[3], h00, h01);
            mma_tf32(d1[nt][0], d1[nt][1], d1[nt][2], d1[nt][3],
                     uh[0], uh[1], uh[2], uh[3], h10, h11);
            mma_tf32(d1[nt][0], d1[nt][1], d1[nt][2], d1[nt][3],
                     uh[0], uh[1], uh[2], uh[3], l10, l11);
            mma_tf32(d1[nt][0], d1[nt][1], d1[nt][2], d1[nt][3],
                     ul[0], ul[1], ul[2], ul[3], h10, h11);
        }
    }

    const float scale = 0.125f;   // 1/sqrt(64)
    #pragma unroll
    for (int nt = 0; nt < 4; nt++) {
        #pragma unroll
        for (int j = 0; j < 4; j++) {
            int r = ub + warpB * 16 + rq + ((j >= 2) ? 8 : 0);
            int p = pb + warpP * 32 + nt * 8 + kc * 2 + (j & 1);
            if (p < P_N) {
                float z  = (l0[nt][j] - l1[nt][j]) * scale;
                float a0 = 1.f / (1.f + expf(-z));
                scores[(size_t)r * P_N + p] = a0 * d0[nt][j] + (1.f - a0) * d1[nt][j];
            }
        }
    }
}

// ---------------- launch -----------------------------------------------------
extern "C" void kernel_launch(void* const* d_in, const int* in_sizes, int n_in,
                              void* d_out, int out_size)
{
    const float* A_up = (const float*)d_in[0];
    const float* A_gu = (const float*)d_in[1];
    const float* A_gp = (const float*)d_in[2];
    const float* ue   = (const float*)d_in[3];
    const float* pe   = (const float*)d_in[4];
    const float* ge   = (const float*)d_in[5];
    const float* W    = (const float*)d_in[6];
    const int*   uids = (const int*)d_in[7];
    float* out = (float*)d_out;

    float *pXup, *pXgu, *pXgp, *pRup, *pRgu, *pRgp, *pdeg;
    cudaGetSymbolAddress((void**)&pXup, g_Xup);
    cudaGetSymbolAddress((void**)&pXgu, g_Xgu);
    cudaGetSymbolAddress((void**)&pXgp, g_Xgp);
    cudaGetSymbolAddress((void**)&pRup, g_Rup);
    cudaGetSymbolAddress((void**)&pRgu, g_Rgu);
    cudaGetSymbolAddress((void**)&pRgp, g_Rgp);
    cudaGetSymbolAddress((void**)&pdeg, g_deg);

    cudaFuncSetAttribute(score_all, cudaFuncAttributeMaxDynamicSharedMemorySize, S_SMEM_BYTES);

    init_all<<<(NUP * D + 255) / 256, 256>>>(ue, pe, ge);

    gemm_all<<<NBLK, 256>>>(A_up, A_gu, A_gp,
                            pXup, pXgu, pXgp,
                            pRup, pRgu, pRgp, pdeg);

    epilogue_all<<<(NTOT * D + 255) / 256, 256>>>();

    uf_q_kernel<<<B_N, D>>>(uids, W, out + (size_t)B_N * P_N);

    dim3 sg((P_N + 63) / 64, B_N / 64);
    score_all<<<sg, 256, S_SMEM_BYTES>>>(out);
}

// round 6
// speedup vs baseline: 1.1699x; 1.1699x over previous
#include <cuda_runtime.h>
#include <math.h>
#include <stdint.h>

#define U_N 4000
#define P_N 4000
#define G_N 200
#define D   64
#define B_N 512
#define NUP (U_N + P_N)   // 8000
#define NGU (G_N + U_N)   // 4200
#define NGP (G_N + P_N)   // 4200
#define NTOT (NUP + NGU + NGP)

// ---------------- scratch (device globals; no allocation allowed) ----------
__device__ __align__(16) float g_Xup[NUP * D];
__device__ __align__(16) float g_Xgu[NGU * D];
__device__ __align__(16) float g_Xgp[NGP * D];
__device__ __align__(16) float g_Rup[NUP * D];
__device__ __align__(16) float g_Rgu[NGU * D];
__device__ __align__(16) float g_Rgp[NGP * D];
__device__ float g_deg[NTOT];
__device__ __align__(16) float g_uf[B_N * D];
__device__ __align__(16) float g_q [B_N * D];

// ---------------- init (float4): zero accumulators + build concat X --------
__global__ void init_all(const float4* __restrict__ ue,
                         const float4* __restrict__ pe,
                         const float4* __restrict__ ge)
{
    int i = blockIdx.x * blockDim.x + threadIdx.x;   // float4 index
    const float4 z4 = make_float4(0.f, 0.f, 0.f, 0.f);
    if (i < NUP * (D / 4)) {
        ((float4*)g_Rup)[i] = z4;
        ((float4*)g_Xup)[i] = (i < U_N * (D / 4)) ? ue[i] : pe[i - U_N * (D / 4)];
    }
    if (i < NGU * (D / 4)) {
        ((float4*)g_Rgu)[i] = z4;
        ((float4*)g_Rgp)[i] = z4;
        ((float4*)g_Xgu)[i] = (i < G_N * (D / 4)) ? ge[i] : ue[i - G_N * (D / 4)];
        ((float4*)g_Xgp)[i] = (i < G_N * (D / 4)) ? ge[i] : pe[i - G_N * (D / 4)];
    }
    if (i < NTOT) g_deg[i] = 0.f;
}

// ---------------- helpers ----------------------------------------------------
__device__ __forceinline__ unsigned smem_u32(const void* p)
{
    return (unsigned)__cvta_generic_to_shared(p);
}
__device__ __forceinline__ void mbar_init(unsigned mb, int count)
{
    asm volatile("mbarrier.init.shared.b64 [%0], %1;" :: "r"(mb), "r"(count) : "memory");
}
__device__ __forceinline__ void mbar_expect_tx(unsigned mb, unsigned bytes)
{
    asm volatile("mbarrier.arrive.expect_tx.shared.b64 _, [%0], %1;"
                 :: "r"(mb), "r"(bytes) : "memory");
}
__device__ __forceinline__ void mbar_wait(unsigned mb, int phase)
{
    asm volatile(
        "{\n\t"
        ".reg .pred P;\n\t"
        "W_%=:\n\t"
        "mbarrier.try_wait.parity.acquire.cta.shared::cta.b64 P, [%0], %1, 0x989680;\n\t"
        "@P bra D_%=;\n\t"
        "bra W_%=;\n\t"
        "D_%=:\n\t"
        "}"
        :: "r"(mb), "r"(phase) : "memory");
}
__device__ __forceinline__ void bulk_cp(unsigned smem_dst, const void* gmem_src,
                                        unsigned bytes, unsigned mb)
{
    asm volatile(
        "cp.async.bulk.shared::cluster.global.mbarrier::complete_tx::bytes [%0], [%1], %2, [%3];"
        :: "r"(smem_dst), "l"(gmem_src), "r"(bytes), "r"(mb) : "memory");
}
__device__ __forceinline__ void mma_tf32(
    float& c0, float& c1, float& c2, float& c3,
    unsigned a0, unsigned a1, unsigned a2, unsigned a3,
    unsigned b0, unsigned b1)
{
    asm volatile(
        "mma.sync.aligned.m16n8k8.row.col.f32.tf32.tf32.f32 "
        "{%0,%1,%2,%3}, {%4,%5,%6,%7}, {%8,%9}, {%0,%1,%2,%3};\n"
        : "+f"(c0), "+f"(c1), "+f"(c2), "+f"(c3)
        : "r"(a0), "r"(a1), "r"(a2), "r"(a3), "r"(b0), "r"(b1));
}

// ---------------- propagation GEMM ------------------------------------------
// R += A@X (tf32 MMA), deg += rowsum(A). All operands staged via cp.async.bulk
// (one 256B bulk op per row -> beats the per-thread LSU issue cap).
// Tile BM=128 x 64, BK=64. 128 thr = 4 warps x 32 rows (2 m-frags each).
#define BM 128
#define BKK 64
#define ASTR 68
#define XSTR 72
#define A_SZ (BM * ASTR)           // 8704 floats
#define X_SZ (BKK * XSTR)          // 4608 floats
#define STG (A_SZ + X_SZ)          // 13312 floats = 53248 B
#define G_SMEM_BYTES (2 * STG * 4) // 106496 B

#define RT0 63
#define RT12 33
#define KS0 8
#define KS12 4
#define NB0 (RT0 * KS0)        // 504
#define NB12 (RT12 * KS12)     // 132
#define NBLK (NB0 + 2 * NB12)  // 768

__device__ __forceinline__ void issue_stage(
    float* Abuf, float* Xbuf, unsigned mb,
    const float* __restrict__ A, const float* __restrict__ X,
    int n, int rowBase, int k0, int kEnd, int tid)
{
    const int kChunk = min(BKK, kEnd - k0);
    const unsigned kBytes = (unsigned)kChunk * 4u;
    if (tid == 0) {
        int nA = min(BM, n - rowBase);
        mbar_expect_tx(mb, (unsigned)nA * kBytes + (unsigned)kChunk * 256u);
    }
    {   // A: one bulk op per row (contiguous kBytes)
        int gr = rowBase + tid;
        if (gr < n)
            bulk_cp(smem_u32(Abuf + tid * ASTR), A + (size_t)gr * n + k0, kBytes, mb);
    }
    if (tid < kChunk)   // X: one bulk op per k-row (256 B)
        bulk_cp(smem_u32(Xbuf + tid * XSTR), X + (size_t)(k0 + tid) * D, 256u, mb);
}

extern "C" __global__ void __launch_bounds__(128, 2)
gemm_all(const float* __restrict__ A0, const float* __restrict__ A1,
         const float* __restrict__ A2,
         const float* __restrict__ X0, const float* __restrict__ X1,
         const float* __restrict__ X2,
         float* __restrict__ R0, float* __restrict__ R1, float* __restrict__ R2,
         float* __restrict__ degAll)
{
    extern __shared__ float dyn[];
    __shared__ uint64_t mbar[2];

    float* AbufS[2] = { dyn,        dyn + STG };
    float* XbufS[2] = { dyn + A_SZ, dyn + STG + A_SZ };

    const int tid  = threadIdx.x;
    const int lane = tid & 31;
    const int warp = tid >> 5;
    const int rq   = lane >> 2;
    const int kc   = lane & 3;
    const int wrow = warp * 32;

    // ---- map block -> (problem, rowTile, ksplit) ----
    const float *A, *X; float *R, *deg;
    int n, rowTiles, kIters, kps, local;
    int b = blockIdx.x;
    if (b < NB0)             { A = A0; X = X0; R = R0; deg = degAll;             n = NUP; rowTiles = RT0;  kIters = 125; kps = 16; local = b; }
    else if (b < NB0 + NB12) { A = A1; X = X1; R = R1; deg = degAll + NUP;       n = NGU; rowTiles = RT12; kIters = 66;  kps = 17; local = b - NB0; }
    else                     { A = A2; X = X2; R = R2; deg = degAll + NUP + NGU; n = NGP; rowTiles = RT12; kIters = 66;  kps = 17; local = b - NB0 - NB12; }

    const int rowTile = local % rowTiles;
    const int split   = local / rowTiles;
    const int rowBase = rowTile * BM;
    const int itStart = split * kps;
    const int itEnd   = min(kIters, itStart + kps);
    const int nIt     = itEnd - itStart;
    if (nIt <= 0) return;
    const int kEnd = min(n, itEnd * BKK);

    if (tid == 0) { mbar_init(smem_u32(&mbar[0]), 1); mbar_init(smem_u32(&mbar[1]), 1); }
    __syncthreads();

    issue_stage(AbufS[0], XbufS[0], smem_u32(&mbar[0]), A, X, n, rowBase,
                itStart * BKK, kEnd, tid);

    float c0[8][4], c1[8][4];
    #pragma unroll
    for (int nt = 0; nt < 8; nt++)
        #pragma unroll
        for (int j = 0; j < 4; j++) { c0[nt][j] = 0.f; c1[nt][j] = 0.f; }
    float dacc[2][2] = {{0.f, 0.f}, {0.f, 0.f}};

    const int r00 = rowBase + wrow + rq;        // m-frag 0 rows: r00, r00+8
    const int r10 = r00 + 16;                   // m-frag 1 rows: r10, r10+8
    int ph0 = 0, ph1 = 0;

    for (int i = 0; i < nIt; i++) {
        const int cur = i & 1;
        const int k0  = (itStart + i) * BKK;

        if (i + 1 < nIt)
            issue_stage(AbufS[cur ^ 1], XbufS[cur ^ 1], smem_u32(&mbar[cur ^ 1]),
                        A, X, n, rowBase, k0 + BKK, kEnd, tid);

        if (cur == 0) { mbar_wait(smem_u32(&mbar[0]), ph0); ph0 ^= 1; }
        else          { mbar_wait(smem_u32(&mbar[1]), ph1); ph1 ^= 1; }

        const float* Ab = AbufS[cur];
        const float* Xb = XbufS[cur];
        const int kSteps = min(BKK, kEnd - k0) >> 3;

        if (kSteps == 8) {
            #pragma unroll
            for (int ks = 0; ks < 8; ks++) {
                const int kb = ks * 8;
                unsigned a0[4], a1[4];
                const int base0 = (wrow + rq) * ASTR + kb + kc;
                a0[0] = __float_as_uint(Ab[base0]);
                a0[1] = __float_as_uint(Ab[base0 + 8 * ASTR]);
                a0[2] = __float_as_uint(Ab[base0 + 4]);
                a0[3] = __float_as_uint(Ab[base0 + 8 * ASTR + 4]);
                const int base1 = base0 + 16 * ASTR;
                a1[0] = __float_as_uint(Ab[base1]);
                a1[1] = __float_as_uint(Ab[base1 + 8 * ASTR]);
                a1[2] = __float_as_uint(Ab[base1 + 4]);
                a1[3] = __float_as_uint(Ab[base1 + 8 * ASTR + 4]);
                dacc[0][0] += __uint_as_float(a0[0]) + __uint_as_float(a0[2]);
                dacc[0][1] += __uint_as_float(a0[1]) + __uint_as_float(a0[3]);
                dacc[1][0] += __uint_as_float(a1[0]) + __uint_as_float(a1[2]);
                dacc[1][1] += __uint_as_float(a1[1]) + __uint_as_float(a1[3]);
                #pragma unroll
                for (int nt = 0; nt < 8; nt++) {
                    unsigned b0 = __float_as_uint(Xb[(kb + kc) * XSTR + nt * 8 + rq]);
                    unsigned b1 = __float_as_uint(Xb[(kb + kc + 4) * XSTR + nt * 8 + rq]);
                    mma_tf32(c0[nt][0], c0[nt][1], c0[nt][2], c0[nt][3],
                             a0[0], a0[1], a0[2], a0[3], b0, b1);
                    mma_tf32(c1[nt][0], c1[nt][1], c1[nt][2], c1[nt][3],
                             a1[0], a1[1], a1[2], a1[3], b0, b1);
                }
            }
        } else {
            for (int ks = 0; ks < kSteps; ks++) {
                const int kb = ks * 8;
                unsigned a0[4], a1[4];
                const int base0 = (wrow + rq) * ASTR + kb + kc;
                a0[0] = __float_as_uint(Ab[base0]);
                a0[1] = __float_as_uint(Ab[base0 + 8 * ASTR]);
                a0[2] = __float_as_uint(Ab[base0 + 4]);
                a0[3] = __float_as_uint(Ab[base0 + 8 * ASTR + 4]);
                const int base1 = base0 + 16 * ASTR;
                a1[0] = __float_as_uint(Ab[base1]);
                a1[1] = __float_as_uint(Ab[base1 + 8 * ASTR]);
                a1[2] = __float_as_uint(Ab[base1 + 4]);
                a1[3] = __float_as_uint(Ab[base1 + 8 * ASTR + 4]);
                dacc[0][0] += __uint_as_float(a0[0]) + __uint_as_float(a0[2]);
                dacc[0][1] += __uint_as_float(a0[1]) + __uint_as_float(a0[3]);
                dacc[1][0] += __uint_as_float(a1[0]) + __uint_as_float(a1[2]);
                dacc[1][1] += __uint_as_float(a1[1]) + __uint_as_float(a1[3]);
                #pragma unroll
                for (int nt = 0; nt < 8; nt++) {
                    unsigned b0 = __float_as_uint(Xb[(kb + kc) * XSTR + nt * 8 + rq]);
                    unsigned b1 = __float_as_uint(Xb[(kb + kc + 4) * XSTR + nt * 8 + rq]);
                    mma_tf32(c0[nt][0], c0[nt][1], c0[nt][2], c0[nt][3],
                             a0[0], a0[1], a0[2], a0[3], b0, b1);
                    mma_tf32(c1[nt][0], c1[nt][1], c1[nt][2], c1[nt][3],
                             a1[0], a1[1], a1[2], a1[3], b0, b1);
                }
            }
        }
        __syncthreads();   // release buffer for re-fill
    }

    // ---- deg: reduce over the 4 kc lanes, one atomic per row ----
    #pragma unroll
    for (int mt = 0; mt < 2; mt++) {
        float v0 = dacc[mt][0], v1 = dacc[mt][1];
        v0 += __shfl_xor_sync(0xffffffffu, v0, 1);
        v0 += __shfl_xor_sync(0xffffffffu, v0, 2);
        v1 += __shfl_xor_sync(0xffffffffu, v1, 1);
        v1 += __shfl_xor_sync(0xffffffffu, v1, 2);
        int r = (mt == 0) ? r00 : r10;
        if (kc == 0) {
            if (r < n)     atomicAdd(&deg[r], v0);
            if (r + 8 < n) atomicAdd(&deg[r + 8], v1);
        }
    }

    // ---- accumulate split-K partials ----
    const int ccBase = kc * 2;
    #pragma unroll
    for (int mt = 0; mt < 2; mt++) {
        const int r = (mt == 0) ? r00 : r10;
        float (*cc)[4] = (mt == 0) ? c0 : c1;
        #pragma unroll
        for (int nt = 0; nt < 8; nt++) {
            int col = nt * 8 + ccBase;
            if (r < n) {
                atomicAdd(&R[r * D + col],     cc[nt][0]);
                atomicAdd(&R[r * D + col + 1], cc[nt][1]);
            }
            if (r + 8 < n) {
                atomicAdd(&R[(r + 8) * D + col],     cc[nt][2]);
                atomicAdd(&R[(r + 8) * D + col + 1], cc[nt][3]);
            }
        }
    }
}

// ---------------- epilogue (float4): R = (X + R/max(deg,1e-8)) * 0.5 --------
__global__ void epilogue_all()
{
    int i4 = blockIdx.x * blockDim.x + threadIdx.x;   // float4 index
    if (i4 >= NTOT * (D / 4)) return;
    int row = i4 >> 4;
    float d = fmaxf(g_deg[row], 1e-8f);
    float4 *Rp; const float4 *Xp; int j;
    if (row < NUP) {
        Rp = (float4*)g_Rup; Xp = (const float4*)g_Xup; j = i4;
    } else if (row < NUP + NGU) {
        Rp = (float4*)g_Rgu; Xp = (const float4*)g_Xgu; j = i4 - NUP * (D / 4);
    } else {
        Rp = (float4*)g_Rgp; Xp = (const float4*)g_Xgp; j = i4 - (NUP + NGU) * (D / 4);
    }
    float4 r = Rp[j], x = Xp[j];
    r.x = (x.x + r.x / d) * 0.5f;
    r.y = (x.y + r.y / d) * 0.5f;
    r.z = (x.z + r.z / d) * 0.5f;
    r.w = (x.w + r.w / d) * 0.5f;
    Rp[j] = r;
}

// ---------------- user_feat gather + q = uf @ W (once, fp32) ----------------
__global__ void uf_q_kernel(const int* __restrict__ uids,
                            const float* __restrict__ W,
                            float* __restrict__ out_uf)
{
    __shared__ float sh[D];
    int b = blockIdx.x;
    int d = threadIdx.x;
    int uid = uids[b];
    float v = 0.5f * (g_Rup[uid * D + d] + g_Rgu[(G_N + uid) * D + d]);
    sh[d] = v;
    g_uf[b * D + d] = v;
    out_uf[b * D + d] = v;
    __syncthreads();
    float acc = 0.f;
    #pragma unroll
    for (int k = 0; k < D; k++) acc += sh[k] * W[k * D + d];
    g_q[b * D + d] = acc;
}

// ---------------- score kernel: diff form, 7 MMAs per (ks,nt) ---------------
// z  = q·(i0-i1)          (plain tf32; feeds sigmoid only)
// dd = uf·(i0-i1), d1 = uf·i1   (3xTF32 error-compensated; feed output)
// out = d1 + sigmoid(z/8)·dd
#define SST 72
#define S_SMEM_BYTES (4 * 64 * SST * 4)   // 73728

__device__ __forceinline__ void split13(float x, unsigned& hi, unsigned& lo)
{
    unsigned h = __float_as_uint(x) & 0xFFFFE000u;
    hi = h;
    lo = __float_as_uint(x - __uint_as_float(h));
}

extern "C" __global__ void __launch_bounds__(256, 2)
score_all(float* __restrict__ scores)
{
    extern __shared__ float smem[];
    float* Qs  = smem;                // [64][SST]
    float* Us  = Qs  + 64 * SST;
    float* I1s = Us  + 64 * SST;
    float* IDs = I1s + 64 * SST;      // i0 - i1

    const int tid   = threadIdx.x;
    const int lane  = tid & 31;
    const int warp  = tid >> 5;
    const int warpB = warp >> 1;
    const int warpP = warp & 1;
    const int rq    = lane >> 2;
    const int kc    = lane & 3;
    const int ub    = blockIdx.y * 64;
    const int pb    = blockIdx.x * 64;

    #pragma unroll
    for (int it = 0; it < 4; it++) {
        int slot = tid + it * 256;     // 1024 float4 slots per array
        int r  = slot >> 4;
        int c4 = (slot & 15) << 2;
        float4 q = *reinterpret_cast<const float4*>(&g_q [(size_t)(ub + r) * D + c4]);
        float4 u = *reinterpret_cast<const float4*>(&g_uf[(size_t)(ub + r) * D + c4]);
        *reinterpret_cast<float4*>(&Qs[r * SST + c4]) = q;
        *reinterpret_cast<float4*>(&Us[r * SST + c4]) = u;
        int gp = pb + r;
        float4 v0 = make_float4(0.f, 0.f, 0.f, 0.f), v1 = v0;
        if (gp < P_N) {
            v0 = *reinterpret_cast<const float4*>(&g_Rup[(size_t)(U_N + gp) * D + c4]);
            v1 = *reinterpret_cast<const float4*>(&g_Rgp[(size_t)(G_N + gp) * D + c4]);
        }
        *reinterpret_cast<float4*>(&I1s[r * SST + c4]) = v1;
        float4 dv = make_float4(v0.x - v1.x, v0.y - v1.y, v0.z - v1.z, v0.w - v1.w);
        *reinterpret_cast<float4*>(&IDs[r * SST + c4]) = dv;
    }
    __syncthreads();

    float z[4][4] = {}, dd[4][4] = {}, d1[4][4] = {};
    const int ar = warpB * 16 + rq;

    #pragma unroll
    for (int ks = 0; ks < 8; ks++) {
        int kb = ks * 8;
        unsigned aq[4];
        float uf[4];
        aq[0] = __float_as_uint(Qs[ar * SST + kb + kc]);
        aq[1] = __float_as_uint(Qs[(ar + 8) * SST + kb + kc]);
        aq[2] = __float_as_uint(Qs[ar * SST + kb + kc + 4]);
        aq[3] = __float_as_uint(Qs[(ar + 8) * SST + kb + kc + 4]);
        uf[0] = Us[ar * SST + kb + kc];
        uf[1] = Us[(ar + 8) * SST + kb + kc];
        uf[2] = Us[ar * SST + kb + kc + 4];
        uf[3] = Us[(ar + 8) * SST + kb + kc + 4];
        unsigned uh[4], ul[4];
        #pragma unroll
        for (int j = 0; j < 4; j++) split13(uf[j], uh[j], ul[j]);

        #pragma unroll
        for (int nt = 0; nt < 4; nt++) {
            int col = warpP * 32 + nt * 8 + rq;
            float bd0 = IDs[col * SST + kb + kc];
            float bd1 = IDs[col * SST + kb + kc + 4];
            float b10 = I1s[col * SST + kb + kc];
            float b11 = I1s[col * SST + kb + kc + 4];
            unsigned hd0, ld0, hd1, ld1, h10, l10, h11, l11;
            split13(bd0, hd0, ld0); split13(bd1, hd1, ld1);
            split13(b10, h10, l10); split13(b11, h11, l11);

            // z: plain tf32 on diff
            mma_tf32(z[nt][0], z[nt][1], z[nt][2], z[nt][3],
                     aq[0], aq[1], aq[2], aq[3], hd0, hd1);
            // dd: compensated uf x diff
            mma_tf32(dd[nt][0], dd[nt][1], dd[nt][2], dd[nt][3],
                     uh[0], uh[1], uh[2], uh[3], hd0, hd1);
            mma_tf32(dd[nt][0], dd[nt][1], dd[nt][2], dd[nt][3],
                     uh[0], uh[1], uh[2], uh[3], ld0, ld1);
            mma_tf32(dd[nt][0], dd[nt][1], dd[nt][2], dd[nt][3],
                     ul[0], ul[1], ul[2], ul[3], hd0, hd1);
            // d1: compensated uf x i1
            mma_tf32(d1[nt][0], d1[nt][1], d1[nt][2], d1[nt][3],
                     uh[0], uh[1], uh[2], uh[3], h10, h11);
            mma_tf32(d1[nt][0], d1[nt][1], d1[nt][2], d1[nt][3],
                     uh[0], uh[1], uh[2], uh[3], l10, l11);
            mma_tf32(d1[nt][0], d1[nt][1], d1[nt][2], d1[nt][3],
                     ul[0], ul[1], ul[2], ul[3], h10, h11);
        }
    }

    const float scale = 0.125f;   // 1/sqrt(64)
    #pragma unroll
    for (int nt = 0; nt < 4; nt++) {
        #pragma unroll
        for (int j = 0; j < 4; j++) {
            int r = ub + warpB * 16 + rq + ((j >= 2) ? 8 : 0);
            int p = pb + warpP * 32 + nt * 8 + kc * 2 + (j & 1);
            if (p < P_N) {
                float a0 = 1.f / (1.f + expf(-z[nt][j] * scale));
                scores[(size_t)r * P_N + p] = d1[nt][j] + a0 * dd[nt][j];
            }
        }
    }
}

// ---------------- launch -----------------------------------------------------
extern "C" void kernel_launch(void* const* d_in, const int* in_sizes, int n_in,
                              void* d_out, int out_size)
{
    const float* A_up = (const float*)d_in[0];
    const float* A_gu = (const float*)d_in[1];
    const float* A_gp = (const float*)d_in[2];
    const float* ue   = (const float*)d_in[3];
    const float* pe   = (const float*)d_in[4];
    const float* ge   = (const float*)d_in[5];
    const float* W    = (const float*)d_in[6];
    const int*   uids = (const int*)d_in[7];
    float* out = (float*)d_out;

    float *pXup, *pXgu, *pXgp, *pRup, *pRgu, *pRgp, *pdeg;
    cudaGetSymbolAddress((void**)&pXup, g_Xup);
    cudaGetSymbolAddress((void**)&pXgu, g_Xgu);
    cudaGetSymbolAddress((void**)&pXgp, g_Xgp);
    cudaGetSymbolAddress((void**)&pRup, g_Rup);
    cudaGetSymbolAddress((void**)&pRgu, g_Rgu);
    cudaGetSymbolAddress((void**)&pRgp, g_Rgp);
    cudaGetSymbolAddress((void**)&pdeg, g_deg);

    cudaFuncSetAttribute(gemm_all,  cudaFuncAttributeMaxDynamicSharedMemorySize, G_SMEM_BYTES);
    cudaFuncSetAttribute(score_all, cudaFuncAttributeMaxDynamicSharedMemorySize, S_SMEM_BYTES);

    init_all<<<(NUP * (D / 4) + 255) / 256, 256>>>(
        (const float4*)ue, (const float4*)pe, (const float4*)ge);

    gemm_all<<<NBLK, 128, G_SMEM_BYTES>>>(A_up, A_gu, A_gp,
                                          pXup, pXgu, pXgp,
                                          pRup, pRgu, pRgp, pdeg);

    epilogue_all<<<(NTOT * (D / 4) + 255) / 256, 256>>>();

    uf_q_kernel<<<B_N, D>>>(uids, W, out + (size_t)B_N * P_N);

    dim3 sg((P_N + 63) / 64, B_N / 64);
    score_all<<<sg, 256, S_SMEM_BYTES>>>(out);
}

// round 7
// speedup vs baseline: 1.3516x; 1.1553x over previous
#include <cuda_runtime.h>
#include <math.h>
#include <stdint.h>

#define U_N 4000
#define P_N 4000
#define G_N 200
#define D   64
#define B_N 512
#define NUP (U_N + P_N)   // 8000
#define NGU (G_N + U_N)   // 4200
#define NGP (G_N + P_N)   // 4200
#define NTOT (NUP + NGU + NGP)

// ---------------- scratch (device globals; no allocation allowed) ----------
__device__ __align__(16) float g_Xup[NUP * D];
__device__ __align__(16) float g_Xgu[NGU * D];
__device__ __align__(16) float g_Xgp[NGP * D];
__device__ __align__(16) float g_XT0[D * NUP];   // transposed X (N-major rows)
__device__ __align__(16) float g_XT1[D * NGU];
__device__ __align__(16) float g_XT2[D * NGP];
__device__ __align__(16) float g_Rup[NUP * D];
__device__ __align__(16) float g_Rgu[NGU * D];
__device__ __align__(16) float g_Rgp[NGP * D];
__device__ float g_deg[NTOT];
__device__ __align__(16) float g_uf[B_N * D];
__device__ __align__(16) float g_q [B_N * D];

// ---------------- init: zero R, build X and X^T ------------------------------
__global__ void init_all(const float* __restrict__ ue,
                         const float* __restrict__ pe,
                         const float* __restrict__ ge)
{
    int i = blockIdx.x * blockDim.x + threadIdx.x;   // element index
    if (i < NUP * D) {
        float v = (i < U_N * D) ? ue[i] : pe[i - U_N * D];
        g_Xup[i] = v;
        g_Rup[i] = 0.f;
        g_XT0[(i & 63) * NUP + (i >> 6)] = v;
    }
    if (i < NGU * D) {
        float vu = (i < G_N * D) ? ge[i] : ue[i - G_N * D];
        float vp = (i < G_N * D) ? ge[i] : pe[i - G_N * D];
        g_Xgu[i] = vu;  g_Rgu[i] = 0.f;
        g_Xgp[i] = vp;  g_Rgp[i] = 0.f;
        g_XT1[(i & 63) * NGU + (i >> 6)] = vu;
        g_XT2[(i & 63) * NGP + (i >> 6)] = vp;
    }
    if (i < NTOT) g_deg[i] = 0.f;
}

// ---------------- helpers ----------------------------------------------------
__device__ __forceinline__ unsigned smem_u32(const void* p)
{
    return (unsigned)__cvta_generic_to_shared(p);
}
__device__ __forceinline__ void mbar_init(unsigned mb, int count)
{
    asm volatile("mbarrier.init.shared.b64 [%0], %1;" :: "r"(mb), "r"(count) : "memory");
}
__device__ __forceinline__ void mbar_expect_tx(unsigned mb, unsigned bytes)
{
    asm volatile("mbarrier.arrive.expect_tx.shared.b64 _, [%0], %1;"
                 :: "r"(mb), "r"(bytes) : "memory");
}
__device__ __forceinline__ void mbar_wait(unsigned mb, int phase)
{
    asm volatile(
        "{\n\t"
        ".reg .pred P;\n\t"
        "W_%=:\n\t"
        "mbarrier.try_wait.parity.acquire.cta.shared::cta.b64 P, [%0], %1, 0x989680;\n\t"
        "@P bra D_%=;\n\t"
        "bra W_%=;\n\t"
        "D_%=:\n\t"
        "}"
        :: "r"(mb), "r"(phase) : "memory");
}
__device__ __forceinline__ void bulk_cp(unsigned smem_dst, const void* gmem_src,
                                        unsigned bytes, unsigned mb)
{
    asm volatile(
        "cp.async.bulk.shared::cluster.global.mbarrier::complete_tx::bytes [%0], [%1], %2, [%3];"
        :: "r"(smem_dst), "l"(gmem_src), "r"(bytes), "r"(mb) : "memory");
}
__device__ __forceinline__ void ldsm_x4(unsigned& r0, unsigned& r1,
                                        unsigned& r2, unsigned& r3, unsigned addr)
{
    asm volatile("ldmatrix.sync.aligned.m8n8.x4.shared.b16 {%0,%1,%2,%3}, [%4];"
                 : "=r"(r0), "=r"(r1), "=r"(r2), "=r"(r3) : "r"(addr));
}
__device__ __forceinline__ void mma_tf32(
    float& c0, float& c1, float& c2, float& c3,
    unsigned a0, unsigned a1, unsigned a2, unsigned a3,
    unsigned b0, unsigned b1)
{
    asm volatile(
        "mma.sync.aligned.m16n8k8.row.col.f32.tf32.tf32.f32 "
        "{%0,%1,%2,%3}, {%4,%5,%6,%7}, {%8,%9}, {%0,%1,%2,%3};\n"
        : "+f"(c0), "+f"(c1), "+f"(c2), "+f"(c3)
        : "r"(a0), "r"(a1), "r"(a2), "r"(a3), "r"(b0), "r"(b1));
}

// ---------------- propagation GEMM ------------------------------------------
// R += A@X (tf32 MMA), deg += rowsum(A).
// A and X^T staged via cp.async.bulk; fragments via ldmatrix.x4.b16.
// Tile BM=128 x 64, BK=64. 128 thr = 4 warps x 32 rows (2 m-frags each).
#define BM 128
#define BKK 64
#define ASTR 68                     // floats; 272B rows: 16B aligned, LDSM conflict-free
#define XSTR 68
#define A_SZ (BM * ASTR)            // 8704 floats
#define X_SZ (D * XSTR)             // 4352 floats (64 n-rows x BKK k-cols)
#define STG (A_SZ + X_SZ)           // 13056 floats
#define G_SMEM_BYTES (2 * STG * 4)  // 104448 B

#define RT0 63
#define RT12 33
#define KS0 16
#define KS12 8
#define KPS0 8
#define KPS12 9
#define NB0 (RT0 * KS0)        // 1008
#define NB12 (RT12 * KS12)     // 264
#define NBLK (NB0 + 2 * NB12)  // 1536

__device__ __forceinline__ void issue_stage(
    float* Abuf, float* Xbuf, unsigned mb,
    const float* __restrict__ A, const float* __restrict__ XT,
    int n, int rowBase, int k0, int kEnd, int tid)
{
    const int kChunk = min(BKK, kEnd - k0);
    const unsigned kBytes = (unsigned)kChunk * 4u;   // multiple of 16 (64 or 40 floats)
    if (tid == 0) {
        int nA = min(BM, n - rowBase);
        mbar_expect_tx(mb, (unsigned)nA * kBytes + (unsigned)D * kBytes);
    }
    {   // A: one bulk op per row
        int gr = rowBase + tid;
        if (gr < n)
            bulk_cp(smem_u32(Abuf + tid * ASTR), A + (size_t)gr * n + k0, kBytes, mb);
    }
    if (tid < D)   // X^T: one bulk op per n-row (row stride = n in gmem)
        bulk_cp(smem_u32(Xbuf + tid * XSTR), XT + (size_t)tid * n + k0, kBytes, mb);
}

extern "C" __global__ void __launch_bounds__(128, 2)
gemm_all(const float* __restrict__ A0, const float* __restrict__ A1,
         const float* __restrict__ A2,
         const float* __restrict__ XT0, const float* __restrict__ XT1,
         const float* __restrict__ XT2,
         float* __restrict__ R0, float* __restrict__ R1, float* __restrict__ R2,
         float* __restrict__ degAll)
{
    extern __shared__ float dyn[];
    __shared__ uint64_t mbar[2];

    float* AbufS[2] = { dyn,        dyn + STG };
    float* XbufS[2] = { dyn + A_SZ, dyn + STG + A_SZ };

    const int tid  = threadIdx.x;
    const int lane = tid & 31;
    const int warp = tid >> 5;
    const int rq   = lane >> 2;
    const int kc   = lane & 3;
    const int wrow = warp * 32;

    // ldmatrix per-lane base offsets (bytes, within a stage buffer)
    // A: tiles 0..3 -> rows {0-7, 8-15, 0-7, 8-15}, k-offset {0,0,4,4}
    const unsigned aLaneOff =
        (unsigned)(((lane & 7) + ((lane >> 3) & 1) * 8 + wrow) * ASTR) * 4u
        + (unsigned)(lane >> 4) * 16u;
    // X^T: tiles 0..3 -> n-rows {0-7, 0-7, 8-15, 8-15}, k-offset {0,4,0,4}
    const unsigned xLaneOff =
        (unsigned)(((lane & 7) + (lane >> 4) * 8) * XSTR) * 4u
        + (unsigned)((lane >> 3) & 1) * 16u;

    // ---- map block -> (problem, rowTile, ksplit) ----
    const float *A, *XT; float *R, *deg;
    int n, kIters, kps, rowTile, split;
    int b = blockIdx.x;
    if (b < NB0) {
        A = A0; XT = XT0; R = R0; deg = degAll; n = NUP; kIters = 125; kps = KPS0;
        rowTile = b % RT0; split = b / RT0;
    } else {
        int idx = b - NB0;
        if (idx < NB12) { A = A1; XT = XT1; R = R1; deg = degAll + NUP;       n = NGU; }
        else            { A = A2; XT = XT2; R = R2; deg = degAll + NUP + NGU; n = NGP; idx -= NB12; }
        kIters = 66; kps = KPS12;
        rowTile = idx % RT12; split = idx / RT12;
    }

    const int rowBase = rowTile * BM;
    const int itStart = split * kps;
    const int itEnd   = min(kIters, itStart + kps);
    const int nIt     = itEnd - itStart;
    if (nIt <= 0) return;
    const int kEnd = min(n, itEnd * BKK);

    if (tid == 0) { mbar_init(smem_u32(&mbar[0]), 1); mbar_init(smem_u32(&mbar[1]), 1); }
    __syncthreads();

    issue_stage(AbufS[0], XbufS[0], smem_u32(&mbar[0]), A, XT, n, rowBase,
                itStart * BKK, kEnd, tid);

    float c0[8][4], c1[8][4];
    #pragma unroll
    for (int nt = 0; nt < 8; nt++)
        #pragma unroll
        for (int j = 0; j < 4; j++) { c0[nt][j] = 0.f; c1[nt][j] = 0.f; }
    float dacc[2][2] = {{0.f, 0.f}, {0.f, 0.f}};

    const int r00 = rowBase + wrow + rq;
    const int r10 = r00 + 16;
    int ph0 = 0, ph1 = 0;

    for (int i = 0; i < nIt; i++) {
        const int cur = i & 1;
        const int k0  = (itStart + i) * BKK;

        if (i + 1 < nIt)
            issue_stage(AbufS[cur ^ 1], XbufS[cur ^ 1], smem_u32(&mbar[cur ^ 1]),
                        A, XT, n, rowBase, k0 + BKK, kEnd, tid);

        if (cur == 0) { mbar_wait(smem_u32(&mbar[0]), ph0); ph0 ^= 1; }
        else          { mbar_wait(smem_u32(&mbar[1]), ph1); ph1 ^= 1; }

        const unsigned aBase = smem_u32(AbufS[cur]) + aLaneOff;
        const unsigned xBase = smem_u32(XbufS[cur]) + xLaneOff;
        const int kSteps = min(BKK, kEnd - k0) >> 3;

        #pragma unroll 8
        for (int ks = 0; ks < kSteps; ks++) {
            const unsigned kbB = (unsigned)(ks * 8) * 4u;
            unsigned a0[4], a1[4];
            ldsm_x4(a0[0], a0[1], a0[2], a0[3], aBase + kbB);
            ldsm_x4(a1[0], a1[1], a1[2], a1[3], aBase + 16u * ASTR * 4u + kbB);
            dacc[0][0] += __uint_as_float(a0[0]) + __uint_as_float(a0[2]);
            dacc[0][1] += __uint_as_float(a0[1]) + __uint_as_float(a0[3]);
            dacc[1][0] += __uint_as_float(a1[0]) + __uint_as_float(a1[2]);
            dacc[1][1] += __uint_as_float(a1[1]) + __uint_as_float(a1[3]);
            #pragma unroll
            for (int p = 0; p < 4; p++) {
                unsigned bx0, bx1, bx2, bx3;   // nt=2p (regs 0,1), nt=2p+1 (regs 2,3)
                ldsm_x4(bx0, bx1, bx2, bx3, xBase + (unsigned)(p * 16 * XSTR) * 4u + kbB);
                mma_tf32(c0[2*p][0], c0[2*p][1], c0[2*p][2], c0[2*p][3],
                         a0[0], a0[1], a0[2], a0[3], bx0, bx1);
                mma_tf32(c0[2*p+1][0], c0[2*p+1][1], c0[2*p+1][2], c0[2*p+1][3],
                         a0[0], a0[1], a0[2], a0[3], bx2, bx3);
                mma_tf32(c1[2*p][0], c1[2*p][1], c1[2*p][2], c1[2*p][3],
                         a1[0], a1[1], a1[2], a1[3], bx0, bx1);
                mma_tf32(c1[2*p+1][0], c1[2*p+1][1], c1[2*p+1][2], c1[2*p+1][3],
                         a1[0], a1[1], a1[2], a1[3], bx2, bx3);
            }
        }
        __syncthreads();   // release buffer for re-fill
    }

    // ---- deg: reduce over the 4 kc lanes, one atomic per row ----
    #pragma unroll
    for (int mt = 0; mt < 2; mt++) {
        float v0 = dacc[mt][0], v1 = dacc[mt][1];
        v0 += __shfl_xor_sync(0xffffffffu, v0, 1);
        v0 += __shfl_xor_sync(0xffffffffu, v0, 2);
        v1 += __shfl_xor_sync(0xffffffffu, v1, 1);
        v1 += __shfl_xor_sync(0xffffffffu, v1, 2);
        int r = (mt == 0) ? r00 : r10;
        if (kc == 0) {
            if (r < n)     atomicAdd(&deg[r], v0);
            if (r + 8 < n) atomicAdd(&deg[r + 8], v1);
        }
    }

    // ---- accumulate split-K partials ----
    const int ccBase = kc * 2;
    #pragma unroll
    for (int mt = 0; mt < 2; mt++) {
        const int r = (mt == 0) ? r00 : r10;
        float (*cc)[4] = (mt == 0) ? c0 : c1;
        #pragma unroll
        for (int nt = 0; nt < 8; nt++) {
            int col = nt * 8 + ccBase;
            if (r < n) {
                atomicAdd(&R[r * D + col],     cc[nt][0]);
                atomicAdd(&R[r * D + col + 1], cc[nt][1]);
            }
            if (r + 8 < n) {
                atomicAdd(&R[(r + 8) * D + col],     cc[nt][2]);
                atomicAdd(&R[(r + 8) * D + col + 1], cc[nt][3]);
            }
        }
    }
}

// ---------------- epilogue (float4): R = (X + R/max(deg,1e-8)) * 0.5 --------
__global__ void epilogue_all()
{
    int i4 = blockIdx.x * blockDim.x + threadIdx.x;   // float4 index
    if (i4 >= NTOT * (D / 4)) return;
    int row = i4 >> 4;
    float d = fmaxf(g_deg[row], 1e-8f);
    float4 *Rp; const float4 *Xp; int j;
    if (row < NUP) {
        Rp = (float4*)g_Rup; Xp = (const float4*)g_Xup; j = i4;
    } else if (row < NUP + NGU) {
        Rp = (float4*)g_Rgu; Xp = (const float4*)g_Xgu; j = i4 - NUP * (D / 4);
    } else {
        Rp = (float4*)g_Rgp; Xp = (const float4*)g_Xgp; j = i4 - (NUP + NGU) * (D / 4);
    }
    float4 r = Rp[j], x = Xp[j];
    r.x = (x.x + r.x / d) * 0.5f;
    r.y = (x.y + r.y / d) * 0.5f;
    r.z = (x.z + r.z / d) * 0.5f;
    r.w = (x.w + r.w / d) * 0.5f;
    Rp[j] = r;
}

// ---------------- user_feat gather + q = uf @ W (once, fp32) ----------------
__global__ void uf_q_kernel(const int* __restrict__ uids,
                            const float* __restrict__ W,
                            float* __restrict__ out_uf)
{
    __shared__ float sh[D];
    int b = blockIdx.x;
    int d = threadIdx.x;
    int uid = uids[b];
    float v = 0.5f * (g_Rup[uid * D + d] + g_Rgu[(G_N + uid) * D + d]);
    sh[d] = v;
    g_uf[b * D + d] = v;
    out_uf[b * D + d] = v;
    __syncthreads();
    float acc = 0.f;
    #pragma unroll
    for (int k = 0; k < D; k++) acc += sh[k] * W[k * D + d];
    g_q[b * D + d] = acc;
}

// ---------------- score kernel: diff form, 7 MMAs per (ks,nt) ---------------
// z  = q·(i0-i1)          (plain tf32; feeds sigmoid only)
// dd = uf·(i0-i1), d1 = uf·i1   (3xTF32 error-compensated; feed output)
// out = d1 + sigmoid(z/8)·dd
#define SST 72
#define S_SMEM_BYTES (4 * 64 * SST * 4)   // 73728

__device__ __forceinline__ void split13(float x, unsigned& hi, unsigned& lo)
{
    unsigned h = __float_as_uint(x) & 0xFFFFE000u;
    hi = h;
    lo = __float_as_uint(x - __uint_as_float(h));
}

extern "C" __global__ void __launch_bounds__(256, 2)
score_all(float* __restrict__ scores)
{
    extern __shared__ float smem[];
    float* Qs  = smem;                // [64][SST]
    float* Us  = Qs  + 64 * SST;
    float* I1s = Us  + 64 * SST;
    float* IDs = I1s + 64 * SST;      // i0 - i1

    const int tid   = threadIdx.x;
    const int lane  = tid & 31;
    const int warp  = tid >> 5;
    const int warpB = warp >> 1;
    const int warpP = warp & 1;
    const int rq    = lane >> 2;
    const int kc    = lane & 3;
    const int ub    = blockIdx.y * 64;
    const int pb    = blockIdx.x * 64;

    #pragma unroll
    for (int it = 0; it < 4; it++) {
        int slot = tid + it * 256;
        int r  = slot >> 4;
        int c4 = (slot & 15) << 2;
        float4 q = *reinterpret_cast<const float4*>(&g_q [(size_t)(ub + r) * D + c4]);
        float4 u = *reinterpret_cast<const float4*>(&g_uf[(size_t)(ub + r) * D + c4]);
        *reinterpret_cast<float4*>(&Qs[r * SST + c4]) = q;
        *reinterpret_cast<float4*>(&Us[r * SST + c4]) = u;
        int gp = pb + r;
        float4 v0 = make_float4(0.f, 0.f, 0.f, 0.f), v1 = v0;
        if (gp < P_N) {
            v0 = *reinterpret_cast<const float4*>(&g_Rup[(size_t)(U_N + gp) * D + c4]);
            v1 = *reinterpret_cast<const float4*>(&g_Rgp[(size_t)(G_N + gp) * D + c4]);
        }
        *reinterpret_cast<float4*>(&I1s[r * SST + c4]) = v1;
        float4 dv = make_float4(v0.x - v1.x, v0.y - v1.y, v0.z - v1.z, v0.w - v1.w);
        *reinterpret_cast<float4*>(&IDs[r * SST + c4]) = dv;
    }
    __syncthreads();

    float z[4][4] = {}, dd[4][4] = {}, d1[4][4] = {};
    const int ar = warpB * 16 + rq;

    #pragma unroll
    for (int ks = 0; ks < 8; ks++) {
        int kb = ks * 8;
        unsigned aq[4];
        float uf[4];
        aq[0] = __float_as_uint(Qs[ar * SST + kb + kc]);
        aq[1] = __float_as_uint(Qs[(ar + 8) * SST + kb + kc]);
        aq[2] = __float_as_uint(Qs[ar * SST + kb + kc + 4]);
        aq[3] = __float_as_uint(Qs[(ar + 8) * SST + kb + kc + 4]);
        uf[0] = Us[ar * SST + kb + kc];
        uf[1] = Us[(ar + 8) * SST + kb + kc];
        uf[2] = Us[ar * SST + kb + kc + 4];
        uf[3] = Us[(ar + 8) * SST + kb + kc + 4];
        unsigned uh[4], ul[4];
        #pragma unroll
        for (int j = 0; j < 4; j++) split13(uf[j], uh[j], ul[j]);

        #pragma unroll
        for (int nt = 0; nt < 4; nt++) {
            int col = warpP * 32 + nt * 8 + rq;
            float bd0 = IDs[col * SST + kb + kc];
            float bd1 = IDs[col * SST + kb + kc + 4];
            float b10 = I1s[col * SST + kb + kc];
            float b11 = I1s[col * SST + kb + kc + 4];
            unsigned hd0, ld0, hd1, ld1, h10, l10, h11, l11;
            split13(bd0, hd0, ld0); split13(bd1, hd1, ld1);
            split13(b10, h10, l10); split13(b11, h11, l11);

            mma_tf32(z[nt][0], z[nt][1], z[nt][2], z[nt][3],
                     aq[0], aq[1], aq[2], aq[3], hd0, hd1);
            mma_tf32(dd[nt][0], dd[nt][1], dd[nt][2], dd[nt][3],
                     uh[0], uh[1], uh[2], uh[3], hd0, hd1);
            mma_tf32(dd[nt][0], dd[nt][1], dd[nt][2], dd[nt][3],
                     uh[0], uh[1], uh[2], uh[3], ld0, ld1);
            mma_tf32(dd[nt][0], dd[nt][1], dd[nt][2], dd[nt][3],
                     ul[0], ul[1], ul[2], ul[3], hd0, hd1);
            mma_tf32(d1[nt][0], d1[nt][1], d1[nt][2], d1[nt][3],
                     uh[0], uh[1], uh[2], uh[3], h10, h11);
            mma_tf32(d1[nt][0], d1[nt][1], d1[nt][2], d1[nt][3],
                     uh[0], uh[1], uh[2], uh[3], l10, l11);
            mma_tf32(d1[nt][0], d1[nt][1], d1[nt][2], d1[nt][3],
                     ul[0], ul[1], ul[2], ul[3], h10, h11);
        }
    }

    const float scale = 0.125f;   // 1/sqrt(64)
    #pragma unroll
    for (int nt = 0; nt < 4; nt++) {
        #pragma unroll
        for (int j = 0; j < 4; j++) {
            int r = ub + warpB * 16 + rq + ((j >= 2) ? 8 : 0);
            int p = pb + warpP * 32 + nt * 8 + kc * 2 + (j & 1);
            if (p < P_N) {
                float a0 = 1.f / (1.f + expf(-z[nt][j] * scale));
                scores[(size_t)r * P_N + p] = d1[nt][j] + a0 * dd[nt][j];
            }
        }
    }
}

// ---------------- launch -----------------------------------------------------
extern "C" void kernel_launch(void* const* d_in, const int* in_sizes, int n_in,
                              void* d_out, int out_size)
{
    const float* A_up = (const float*)d_in[0];
    const float* A_gu = (const float*)d_in[1];
    const float* A_gp = (const float*)d_in[2];
    const float* ue   = (const float*)d_in[3];
    const float* pe   = (const float*)d_in[4];
    const float* ge   = (const float*)d_in[5];
    const float* W    = (const float*)d_in[6];
    const int*   uids = (const int*)d_in[7];
    float* out = (float*)d_out;

    float *pXT0, *pXT1, *pXT2, *pRup, *pRgu, *pRgp, *pdeg;
    cudaGetSymbolAddress((void**)&pXT0, g_XT0);
    cudaGetSymbolAddress((void**)&pXT1, g_XT1);
    cudaGetSymbolAddress((void**)&pXT2, g_XT2);
    cudaGetSymbolAddress((void**)&pRup, g_Rup);
    cudaGetSymbolAddress((void**)&pRgu, g_Rgu);
    cudaGetSymbolAddress((void**)&pRgp, g_Rgp);
    cudaGetSymbolAddress((void**)&pdeg, g_deg);

    cudaFuncSetAttribute(gemm_all,  cudaFuncAttributeMaxDynamicSharedMemorySize, G_SMEM_BYTES);
    cudaFuncSetAttribute(score_all, cudaFuncAttributeMaxDynamicSharedMemorySize, S_SMEM_BYTES);

    init_all<<<(NUP * D + 255) / 256, 256>>>(ue, pe, ge);

    gemm_all<<<NBLK, 128, G_SMEM_BYTES>>>(A_up, A_gu, A_gp,
                                          pXT0, pXT1, pXT2,
                                          pRup, pRgu, pRgp, pdeg);

    epilogue_all<<<(NTOT * (D / 4) + 255) / 256, 256>>>();

    uf_q_kernel<<<B_N, D>>>(uids, W, out + (size_t)B_N * P_N);

    dim3 sg((P_N + 63) / 64, B_N / 64);
    score_all<<<sg, 256, S_SMEM_BYTES>>>(out);
}